// round 12
// baseline (speedup 1.0000x reference)
#include <cuda_runtime.h>

#define H    4096
#define IN   512
#define OUT  64
#define NJ4  (H / 4)      // 1024 float4 columns total
#define NSTR 592          // A-phase k-stripes (148 SM x 4 = one wave)
#define CF4  512          // f4 columns per chunk (2048 scalars, NCH=2)

// Device-global scratch (no allocations allowed).
__device__ float4   g_part[(size_t)NSTR * CF4];  // ~4.85 MB
__device__ float    g_init[H];                   // bias + i2h
__device__ float    g_x[H];
__device__ unsigned g_flag[2];                   // per-chunk x-done counters

// ---------------------------------------------------------------------------
// Kernel A (chunk c): 592 stripe-blocks compute GEMV partials over the
// chunk's 2048 columns; on c==0, 128 extra blocks compute g_init (i2h+bias)
// and zero the flags. hebb loaded 32B v8 evict_last (stays L2-resident for
// k_XB); w/plas plain float4 (R8-measured fastest combo, 6.3 TB/s).
// ---------------------------------------------------------------------------
__global__ void __launch_bounds__(256)
k_A(const float* __restrict__ hidden, const float* __restrict__ hebb,
    const float* __restrict__ w,      const float* __restrict__ plas,
    const float* __restrict__ inp,    const float* __restrict__ W_i2h,
    const float* __restrict__ b_i2h,  int c) {
    int b = blockIdx.x, t = threadIdx.x;

    if (b < NSTR) {
        int k0 = (b * H) / NSTR;
        int k1 = ((b + 1) * H) / NSTR;        // ~7 rows
        const float4* w4 = (const float4*)w;
        const float4* p4 = (const float4*)plas;
        const float4* h4 = (const float4*)hebb;
        size_t fbase = (size_t)c * CF4 + t * 2;

        float4 acc0 = make_float4(0.f, 0.f, 0.f, 0.f);
        float4 acc1 = make_float4(0.f, 0.f, 0.f, 0.f);
#pragma unroll 4
        for (int r = k0; r < k1; ++r) {
            size_t idx = (size_t)r * NJ4 + fbase;
            float hk = __ldg(hidden + r);
            float4 a0 = w4[idx], a1 = w4[idx + 1];
            float4 b0 = p4[idx], b1 = p4[idx + 1];
            float4 c0, c1;
            asm volatile(
                "ld.global.nc.L2::evict_last.v8.b32 "
                "{%0,%1,%2,%3,%4,%5,%6,%7}, [%8];"
                : "=f"(c0.x), "=f"(c0.y), "=f"(c0.z), "=f"(c0.w),
                  "=f"(c1.x), "=f"(c1.y), "=f"(c1.z), "=f"(c1.w)
                : "l"(h4 + idx));
            acc0.x += hk * fmaf(b0.x, c0.x, a0.x);
            acc0.y += hk * fmaf(b0.y, c0.y, a0.y);
            acc0.z += hk * fmaf(b0.z, c0.z, a0.z);
            acc0.w += hk * fmaf(b0.w, c0.w, a0.w);
            acc1.x += hk * fmaf(b1.x, c1.x, a1.x);
            acc1.y += hk * fmaf(b1.y, c1.y, a1.y);
            acc1.z += hk * fmaf(b1.z, c1.z, a1.z);
            acc1.w += hk * fmaf(b1.w, c1.w, a1.w);
        }
        size_t o = (size_t)b * CF4 + t * 2;
        g_part[o] = acc0;
        g_part[o + 1] = acc1;
    } else {
        // ---- init blocks (only launched on c==0): i2h + bias; zero flags
        if (b == NSTR && t == 0) { g_flag[0] = 0; g_flag[1] = 0; }
        int ib   = b - NSTR;              // 0..127, 32 rows each
        int wrp  = t >> 5, lane = t & 31;
        const float4* in4 = (const float4*)inp;
#pragma unroll
        for (int rr = 0; rr < 4; ++rr) {
            int row = ib * 32 + wrp * 4 + rr;
            const float4* wr = (const float4*)(W_i2h + (size_t)row * IN);
            float d = 0.f;
#pragma unroll
            for (int q = 0; q < (IN / 4) / 32; ++q) {
                float4 aa = wr[lane + q * 32];
                float4 bb = in4[lane + q * 32];
                d += aa.x * bb.x + aa.y * bb.y + aa.z * bb.z + aa.w * bb.w;
            }
#pragma unroll
            for (int o = 16; o; o >>= 1) d += __shfl_down_sync(0xffffffffu, d, o);
            if (lane == 0) g_init[row] = d + b_i2h[row];
        }
    }
}

// ---------------------------------------------------------------------------
// Kernel XB (chunk c): 512 blocks.
//  blocks 0..31   : finalize x for the chunk (reduce 592 partials + g_init,
//                   relu), write g_x/x_out, then bump g_flag[c].
//  (do_out) 32..95: output head, waits on flag (needs full x).
//  rest           : hebb update for the chunk; waits on flag, reads hebb
//                   (L2-resident from k_A), writes hebb_out.
// Producers have the lowest block ids -> scheduled in wave 1 -> no deadlock.
// ---------------------------------------------------------------------------
__device__ __forceinline__ void wait_flag(int c) {
    if (threadIdx.x == 0) {
        volatile unsigned* f = &g_flag[c];
        while (*f < 32u) __nanosleep(32);
    }
    __syncthreads();
    __threadfence();
}

__global__ void __launch_bounds__(256)
k_XB(const float* __restrict__ hidden, const float* __restrict__ hebb,
     const float* __restrict__ learn_p,
     const float* __restrict__ W_h2o,  const float* __restrict__ b_h2o,
     float* __restrict__ out, float* __restrict__ x_out,
     float* __restrict__ hebb_out, int c, int do_out) {
    int b = blockIdx.x, t = threadIdx.x;
    const float4* h4 = (const float4*)hebb;
    const float4* x4 = (const float4*)g_x;

    if (b < 32) {
        // ---- x finalize: block owns 16 f4 cols ----
        __shared__ float4 sred[16][16];
        int cl = t & 15, sl = t >> 4;
        float4 a = make_float4(0.f, 0.f, 0.f, 0.f);
        for (int s = sl; s < NSTR; s += 16) {
            float4 v = g_part[(size_t)s * CF4 + b * 16 + cl];
            a.x += v.x; a.y += v.y; a.z += v.z; a.w += v.w;
        }
        sred[sl][cl] = a;
        __syncthreads();
        if (t < 16) {
            float4 tot = sred[0][t];
#pragma unroll
            for (int g = 1; g < 16; ++g) {
                float4 v = sred[g][t];
                tot.x += v.x; tot.y += v.y; tot.z += v.z; tot.w += v.w;
            }
            int j4g = c * CF4 + b * 16 + t;
            float4 gi = ((const float4*)g_init)[j4g];
            float4 xv;
            xv.x = fmaxf(tot.x + gi.x, 0.f);
            xv.y = fmaxf(tot.y + gi.y, 0.f);
            xv.z = fmaxf(tot.z + gi.z, 0.f);
            xv.w = fmaxf(tot.w + gi.w, 0.f);
            ((float4*)g_x)[j4g]   = xv;
            ((float4*)x_out)[j4g] = xv;
        }
        __syncthreads();
        __threadfence();
        if (t == 0) atomicAdd(&g_flag[c], 1u);
        return;
    }

    if (do_out && b < 96) {
        // ---- output head (needs full x: chunk0 done last kernel, chunk1 here)
        wait_flag(c);
        __shared__ float red[8];
        int o = b - 32;
        const float4* wr = (const float4*)(W_h2o + (size_t)o * H);
        float acc = 0.f;
#pragma unroll
        for (int q = 0; q < NJ4 / 256; ++q) {
            float4 aa = wr[t + q * 256];
            float4 bb = x4[t + q * 256];
            acc += aa.x * bb.x + aa.y * bb.y + aa.z * bb.z + aa.w * bb.w;
        }
#pragma unroll
        for (int s = 16; s; s >>= 1) acc += __shfl_down_sync(0xffffffffu, acc, s);
        if ((t & 31) == 0) red[t >> 5] = acc;
        __syncthreads();
        if (t == 0) {
            float v = red[0] + red[1] + red[2] + red[3] +
                      red[4] + red[5] + red[6] + red[7];
            out[o] = tanhf(v + b_h2o[o]);
        }
        return;
    }

    // ---- hebb update for the chunk ----
    int base = do_out ? 96 : 32;
    int nbh  = 512 - base;               // 416 or 480
    int bb   = b - base;
    wait_flag(c);
    int r0 = (bb * H) / nbh;
    int r1 = ((bb + 1) * H) / nbh;       // ~9-10 rows
    float learn = __ldg(learn_p);
    float am    = 1.f - learn;
    size_t fbase = (size_t)c * CF4 + t * 2;
    float4 xv0 = x4[c * CF4 + t * 2];
    float4 xv1 = x4[c * CF4 + t * 2 + 1];
#pragma unroll 4
    for (int r = r0; r < r1; ++r) {
        size_t idx = (size_t)r * NJ4 + fbase;
        float sc = learn * __ldg(hidden + r);
        float4 hb0 = h4[idx];            // expect L2 hit (read in k_A)
        float4 hb1 = h4[idx + 1];
        float4 o0, o1;
        o0.x = fmaf(am, hb0.x, sc * xv0.x);
        o0.y = fmaf(am, hb0.y, sc * xv0.y);
        o0.z = fmaf(am, hb0.z, sc * xv0.z);
        o0.w = fmaf(am, hb0.w, sc * xv0.w);
        o1.x = fmaf(am, hb1.x, sc * xv1.x);
        o1.y = fmaf(am, hb1.y, sc * xv1.y);
        o1.z = fmaf(am, hb1.z, sc * xv1.z);
        o1.w = fmaf(am, hb1.w, sc * xv1.w);
        ((float4*)hebb_out)[idx]     = o0;
        ((float4*)hebb_out)[idx + 1] = o1;
    }
}

// ---------------------------------------------------------------------------
// Inputs: 0 inp, 1 hidden, 2 hebb, 3 W_i2h, 4 b_i2h, 5 w, 6 plas,
//         7 learn, 8 W_h2o, 9 b_h2o
// Output: [out(64) | x(4096) | hebb_new(16777216)]
// ---------------------------------------------------------------------------
extern "C" void kernel_launch(void* const* d_in, const int* in_sizes, int n_in,
                              void* d_out, int out_size) {
    const float* inp    = (const float*)d_in[0];
    const float* hidden = (const float*)d_in[1];
    const float* hebb   = (const float*)d_in[2];
    const float* W_i2h  = (const float*)d_in[3];
    const float* b_i2h  = (const float*)d_in[4];
    const float* w      = (const float*)d_in[5];
    const float* plas   = (const float*)d_in[6];
    const float* learn  = (const float*)d_in[7];
    const float* W_h2o  = (const float*)d_in[8];
    const float* b_h2o  = (const float*)d_in[9];

    float* out      = (float*)d_out;
    float* x_out    = out + OUT;
    float* hebb_out = out + OUT + H;

    // Chunk 0: GEMV partials (+ i2h & flag init), then x-finalize + hebb half
    k_A<<<NSTR + 128, 256>>>(hidden, hebb, w, plas, inp, W_i2h, b_i2h, 0);
    k_XB<<<512, 256>>>(hidden, hebb, learn, W_h2o, b_h2o,
                       out, x_out, hebb_out, 0, 0);
    // Chunk 1: same + output head
    k_A<<<NSTR, 256>>>(hidden, hebb, w, plas, inp, W_i2h, b_i2h, 1);
    k_XB<<<512, 256>>>(hidden, hebb, learn, W_h2o, b_h2o,
                       out, x_out, hebb_out, 1, 1);
}

// round 13
// speedup vs baseline: 1.3507x; 1.3507x over previous
#include <cuda_runtime.h>

#define H    4096
#define IN   512
#define OUT  64
#define NJ4  (H / 4)       // 1024 float4 columns
#define GY   296           // k-stripes (592 stripe-blocks = 2 per stripe-col)
#define NSB  592           // stripe blocks in kernel 1
#define NRB  128           // reducer blocks appended after them

// Device-global scratch (no allocations allowed).
__device__ float4   g_part[(size_t)GY * NJ4];  // ~4.85 MB
__device__ float    g_x[H];
__device__ unsigned g_done;                    // monotonic: +NSB per launch
__device__ unsigned g_rtkt;                    // monotonic: +NRB per launch

// ---------------------------------------------------------------------------
// Kernel 1: GEMV partials (blocks 0..591, R8's measured-32.6us pattern) +
// x-finalize (blocks 592..719: i2h dot first, then ticket-wait on g_done,
// then partial-reduce + bias + relu). Reducer blocks have the highest bids
// -> scheduled last -> no deadlock; counters are monotonic -> graph-safe.
// ---------------------------------------------------------------------------
__global__ void __launch_bounds__(256)
k_recur_red(const float* __restrict__ hidden, const float* __restrict__ hebb,
            const float* __restrict__ w,      const float* __restrict__ plas,
            const float* __restrict__ inp,    const float* __restrict__ W_i2h,
            const float* __restrict__ b_i2h,  float* __restrict__ x_out) {
    int b = blockIdx.x, t = threadIdx.x;

    if (b < NSB) {
        // ================== GEMV partial (8-wide, v8 evict_last) ==========
        int stripe = b >> 1;
        int j8 = (b & 1) * 256 + t;            // 0..511
        int k0 = (stripe * H) / GY;
        int k1 = ((stripe + 1) * H) / GY;

        const float4* w4 = (const float4*)w;
        const float4* p4 = (const float4*)plas;
        const float4* h4 = (const float4*)hebb;

        float4 acc0 = make_float4(0.f, 0.f, 0.f, 0.f);
        float4 acc1 = make_float4(0.f, 0.f, 0.f, 0.f);
        size_t fbase = (size_t)j8 * 2;
#pragma unroll 4
        for (int r = k0; r < k1; ++r) {
            size_t idx = (size_t)r * NJ4 + fbase;
            float hk = __ldg(hidden + r);
            float4 a0 = w4[idx], a1 = w4[idx + 1];
            float4 b0 = p4[idx], b1 = p4[idx + 1];
            float4 c0, c1;
            asm volatile(
                "ld.global.nc.L2::evict_last.v8.b32 "
                "{%0,%1,%2,%3,%4,%5,%6,%7}, [%8];"
                : "=f"(c0.x), "=f"(c0.y), "=f"(c0.z), "=f"(c0.w),
                  "=f"(c1.x), "=f"(c1.y), "=f"(c1.z), "=f"(c1.w)
                : "l"(h4 + idx));
            acc0.x += hk * fmaf(b0.x, c0.x, a0.x);
            acc0.y += hk * fmaf(b0.y, c0.y, a0.y);
            acc0.z += hk * fmaf(b0.z, c0.z, a0.z);
            acc0.w += hk * fmaf(b0.w, c0.w, a0.w);
            acc1.x += hk * fmaf(b1.x, c1.x, a1.x);
            acc1.y += hk * fmaf(b1.y, c1.y, a1.y);
            acc1.z += hk * fmaf(b1.z, c1.z, a1.z);
            acc1.w += hk * fmaf(b1.w, c1.w, a1.w);
        }
        size_t o = (size_t)stripe * NJ4 + fbase;
        g_part[o]     = acc0;
        g_part[o + 1] = acc1;
        __threadfence();
        __syncthreads();
        if (t == 0) atomicAdd(&g_done, 1u);
        return;
    }

    // ================== Reducer block (x-finalize) ==================
    __shared__ float4 sp[32][8];     // [grp][j4loc]
    __shared__ float  sdot[32];
    __shared__ float4 stot[8];

    int rb = b - NSB;                // 0..127
    int j4base = rb * 8;             // 8 f4 columns = 32 scalar cols

    // ---- i2h dots first (independent of partials; overlaps the wait) ----
    int wrp  = t >> 5;               // 0..7
    int lane = t & 31;
    const float4* in4 = (const float4*)inp;
#pragma unroll
    for (int c = 0; c < 4; ++c) {
        int col = wrp * 4 + c;                       // 0..31
        int j   = j4base * 4 + col;
        const float4* row = (const float4*)(W_i2h + (size_t)j * IN);
        float d = 0.f;
#pragma unroll
        for (int q = 0; q < (IN / 4) / 32; ++q) {
            float4 aa = row[lane + q * 32];
            float4 bb = in4[lane + q * 32];
            d += aa.x * bb.x + aa.y * bb.y + aa.z * bb.z + aa.w * bb.w;
        }
#pragma unroll
        for (int o = 16; o; o >>= 1) d += __shfl_down_sync(0xffffffffu, d, o);
        if (lane == 0) sdot[col] = d;
    }

    // ---- wait until all NSB stripe blocks of THIS launch are done ----
    if (t == 0) {
        unsigned tk = atomicAdd(&g_rtkt, 1u);
        unsigned target = (tk / NRB + 1u) * NSB;
        volatile unsigned* p = &g_done;
        while (*p < target) __nanosleep(64);
    }
    __syncthreads();
    __threadfence();

    // ---- reduce partials (coalesced) ----
    int j4loc = t & 7;
    int grp   = t >> 3;              // 0..31
    float4 acc = make_float4(0.f, 0.f, 0.f, 0.f);
#pragma unroll
    for (int q = 0; q < (GY + 31) / 32; ++q) {
        int kb = grp + 32 * q;
        if (kb < GY) {
            float4 v = g_part[(size_t)kb * NJ4 + j4base + j4loc];
            acc.x += v.x; acc.y += v.y; acc.z += v.z; acc.w += v.w;
        }
    }
    sp[grp][j4loc] = acc;
    __syncthreads();
    if (t < 8) {
        float4 t4 = make_float4(0.f, 0.f, 0.f, 0.f);
#pragma unroll
        for (int g = 0; g < 32; ++g) {
            float4 v = sp[g][t];
            t4.x += v.x; t4.y += v.y; t4.z += v.z; t4.w += v.w;
        }
        stot[t] = t4;
    }
    __syncthreads();
    if (t < 32) {
        int col  = t;
        int jl   = col >> 2;
        int comp = col & 3;
        float4 t4 = stot[jl];
        float part = (comp == 0) ? t4.x : (comp == 1) ? t4.y
                   : (comp == 2) ? t4.z : t4.w;
        int j = j4base * 4 + col;
        float v = fmaxf(part + sdot[col] + b_i2h[j], 0.f);
        g_x[j]   = v;
        x_out[j] = v;
    }
}

// ---------------------------------------------------------------------------
// Kernel 2: hebb update (R1's measured-20.8us config: plain loads/stores,
// natural order) + output head on 64 EXTRA tail blocks (same wave count,
// so the head is effectively free and never delays hebb streamers).
// ---------------------------------------------------------------------------
__global__ void __launch_bounds__(256)
k_hebb_out(const float* __restrict__ hidden,
           const float* __restrict__ hebb,
           const float* __restrict__ learn_p,
           const float* __restrict__ W_h2o,
           const float* __restrict__ b_h2o,
           float* __restrict__ hebb_out,
           float* __restrict__ out) {
    int b = blockIdx.x, t = threadIdx.x;
    const float4* x4 = (const float4*)g_x;

    if (b < (H * H / 4) / 256) {
        // ---- hebb update ----
        size_t idx = (size_t)b * 256 + t;   // float4 index over H*H/4
        int k  = (int)(idx >> 10);
        int jc = (int)(idx & 1023);
        float learn = __ldg(learn_p);
        float hk    = __ldg(hidden + k);
        float4 hb = ((const float4*)hebb)[idx];   // L2 hit if still pinned
        float4 xv = x4[jc];
        float a = 1.f - learn;
        float s = learn * hk;
        float4 o4;
        o4.x = fmaf(a, hb.x, s * xv.x);
        o4.y = fmaf(a, hb.y, s * xv.y);
        o4.z = fmaf(a, hb.z, s * xv.z);
        o4.w = fmaf(a, hb.w, s * xv.w);
        ((float4*)hebb_out)[idx] = o4;
        return;
    }

    // ---- output head (extra tail blocks) ----
    __shared__ float red[8];
    int o = b - (H * H / 4) / 256;          // 0..63
    const float4* wr = (const float4*)(W_h2o + (size_t)o * H);
    float acc = 0.f;
#pragma unroll
    for (int q = 0; q < NJ4 / 256; ++q) {
        float4 aa = wr[t + q * 256];
        float4 bb = x4[t + q * 256];
        acc += aa.x * bb.x + aa.y * bb.y + aa.z * bb.z + aa.w * bb.w;
    }
#pragma unroll
    for (int s = 16; s; s >>= 1) acc += __shfl_down_sync(0xffffffffu, acc, s);
    if ((t & 31) == 0) red[t >> 5] = acc;
    __syncthreads();
    if (t == 0) {
        float v = red[0] + red[1] + red[2] + red[3] +
                  red[4] + red[5] + red[6] + red[7];
        out[o] = tanhf(v + b_h2o[o]);
    }
}

// ---------------------------------------------------------------------------
// Inputs: 0 inp, 1 hidden, 2 hebb, 3 W_i2h, 4 b_i2h, 5 w, 6 plas,
//         7 learn, 8 W_h2o, 9 b_h2o
// Output: [out(64) | x(4096) | hebb_new(16777216)]
// ---------------------------------------------------------------------------
extern "C" void kernel_launch(void* const* d_in, const int* in_sizes, int n_in,
                              void* d_out, int out_size) {
    const float* inp    = (const float*)d_in[0];
    const float* hidden = (const float*)d_in[1];
    const float* hebb   = (const float*)d_in[2];
    const float* W_i2h  = (const float*)d_in[3];
    const float* b_i2h  = (const float*)d_in[4];
    const float* w      = (const float*)d_in[5];
    const float* plas   = (const float*)d_in[6];
    const float* learn  = (const float*)d_in[7];
    const float* W_h2o  = (const float*)d_in[8];
    const float* b_h2o  = (const float*)d_in[9];

    float* out      = (float*)d_out;
    float* x_out    = out + OUT;
    float* hebb_out = out + OUT + H;

    // Kernel 1: GEMV partials + fused x-finalize (tail reducer blocks)
    k_recur_red<<<NSB + NRB, 256>>>(hidden, hebb, w, plas,
                                    inp, W_i2h, b_i2h, x_out);

    // Kernel 2: hebb update + output head
    k_hebb_out<<<(H * H / 4) / 256 + OUT, 256>>>(hidden, hebb, learn,
                                                 W_h2o, b_h2o, hebb_out, out);
}